// round 16
// baseline (speedup 1.0000x reference)
#include <cuda_runtime.h>
#include <cuda_bf16.h>
#include <math.h>
#include <stdint.h>

#define BATCH 2
#define SEQ   2048
#define DIM   768
#define NHEAD 12
#define HDIM  64
#define KVW   128
#define MROWS (BATCH*SEQ)
#define ATT_SCALE_LOG2E 0.1803368801111204f   // 0.125 * log2(e)

typedef __nv_bfloat16 bf16;

// ---------------- scratch ----------------
__device__ bf16 g_xh [(size_t)MROWS * DIM];
__device__ bf16 g_xl [(size_t)MROWS * DIM];
__device__ bf16 g_Wqh[(size_t)DIM * DIM];
__device__ bf16 g_Wql[(size_t)DIM * DIM];
__device__ bf16 g_Wkh[(size_t)DIM * KVW];
__device__ bf16 g_Wkl[(size_t)DIM * KVW];
__device__ bf16 g_Wph[(size_t)DIM * DIM];
__device__ bf16 g_Wpl[(size_t)DIM * DIM];
__device__ bf16 g_Qh [(size_t)MROWS * DIM];
__device__ bf16 g_Ql [(size_t)MROWS * DIM];
__device__ bf16 g_KVh[(size_t)MROWS * KVW];
__device__ bf16 g_KVl[(size_t)MROWS * KVW];
__device__ bf16 g_Oh [(size_t)MROWS * DIM];
__device__ bf16 g_Ol [(size_t)MROWS * DIM];

// ---------------- helpers ----------------
__device__ __forceinline__ uint32_t pack2(float x, float y) {
    __nv_bfloat162 t = __float22bfloat162_rn(make_float2(x, y));
    return *reinterpret_cast<uint32_t*>(&t);
}
__device__ __forceinline__ float2 unpack2(uint32_t u) {
    __nv_bfloat162 t = *reinterpret_cast<__nv_bfloat162*>(&u);
    return __bfloat1622float2(t);
}
__device__ __forceinline__ uint32_t smem_addr(const void* p) {
    return (uint32_t)__cvta_generic_to_shared(p);
}
__device__ __forceinline__ void cp16(bf16* dst, const bf16* src) {
    asm volatile("cp.async.cg.shared.global [%0], [%1], 16;"
                 :: "r"(smem_addr(dst)), "l"(src));
}
#define CP_COMMIT()  asm volatile("cp.async.commit_group;" ::: "memory")
#define CP_WAIT(n)   asm volatile("cp.async.wait_group " #n ";" ::: "memory")
#define EX2F(d, s)   asm("ex2.approx.f32 %0, %1;" : "=f"(d) : "f"(s))

#define MMA_BF16(c, a, b0, b1)                                                   \
    asm volatile("mma.sync.aligned.m16n8k16.row.col.f32.bf16.bf16.f32 "          \
                 "{%0,%1,%2,%3},{%4,%5,%6,%7},{%8,%9},{%0,%1,%2,%3};"            \
                 : "+f"((c)[0]), "+f"((c)[1]), "+f"((c)[2]), "+f"((c)[3])        \
                 : "r"((a)[0]), "r"((a)[1]), "r"((a)[2]), "r"((a)[3]),           \
                   "r"(b0), "r"(b1))

#define LDSM_X4(r, addr)                                                         \
    asm volatile("ldmatrix.sync.aligned.m8n8.x4.shared.b16 {%0,%1,%2,%3}, [%4];" \
                 : "=r"((r)[0]), "=r"((r)[1]), "=r"((r)[2]), "=r"((r)[3])        \
                 : "r"(addr))
#define LDSM_X4T(r, addr)                                                        \
    asm volatile("ldmatrix.sync.aligned.m8n8.x4.trans.shared.b16 {%0,%1,%2,%3}, [%4];" \
                 : "=r"((r)[0]), "=r"((r)[1]), "=r"((r)[2]), "=r"((r)[3])        \
                 : "r"(addr))

// ---------------------------------------------------------------------------
// Fused fp32 -> split bf16 for all 4 tensors.
// ---------------------------------------------------------------------------
#define X4SZ 786432
#define Q4SZ 147456
#define K4SZ 24576
#define CVT_TOTAL (X4SZ + Q4SZ + K4SZ + Q4SZ)

__global__ void cvt_all(const float* __restrict__ x,  const float* __restrict__ Wq,
                        const float* __restrict__ Wkv, const float* __restrict__ Wp,
                        bf16* __restrict__ xh,  bf16* __restrict__ xl,
                        bf16* __restrict__ Wqh, bf16* __restrict__ Wql,
                        bf16* __restrict__ Wkh, bf16* __restrict__ Wkl,
                        bf16* __restrict__ Wph, bf16* __restrict__ Wpl)
{
    int i = blockIdx.x * blockDim.x + threadIdx.x;
    const float* src; bf16 *h, *l; int j = i;
    if (j < X4SZ) { src = x; h = xh; l = xl; }
    else {
        j -= X4SZ;
        if (j < Q4SZ) { src = Wq; h = Wqh; l = Wql; }
        else {
            j -= Q4SZ;
            if (j < K4SZ) { src = Wkv; h = Wkh; l = Wkl; }
            else { j -= K4SZ; src = Wp; h = Wph; l = Wpl; }
        }
    }
    float4 v = ((const float4*)src)[j];
    uint32_t h0 = pack2(v.x, v.y), h1 = pack2(v.z, v.w);
    float2 f0 = unpack2(h0), f1 = unpack2(h1);
    uint32_t l0 = pack2(v.x - f0.x, v.y - f0.y), l1 = pack2(v.z - f1.x, v.w - f1.y);
    ((uint2*)h)[j] = make_uint2(h0, h1);
    ((uint2*)l)[j] = make_uint2(l0, l1);
}

// ---------------------------------------------------------------------------
// Split-bf16 GEMM, 128x64 tile, BK=32, cp.async double buffer, 3 CTAs/SM.
// B hi+lo fragments loaded with ONE ldmatrix.x4.trans (lanes 0-15: Bh, 16-31: Bl).
// ---------------------------------------------------------------------------
#define ASTR 40
#define BSTR 72
#define G_SAL 5120
#define G_SBH 10240
#define G_SBL 12544
#define G_STG 14848
#define GEMM_SMEM_BYTES (2 * G_STG * 2)

__global__ __launch_bounds__(256, 3)
void gemm_bf16(const bf16* __restrict__ Ah, const bf16* __restrict__ Al,
               const bf16* __restrict__ B1h, const bf16* __restrict__ B1l, int N1,
               const bf16* __restrict__ B2h, const bf16* __restrict__ B2l, int N2,
               int M, int K,
               float* __restrict__ Cf, const float* __restrict__ bias,
               bf16* __restrict__ C1h, bf16* __restrict__ C1l, float scale1,
               bf16* __restrict__ C2h, bf16* __restrict__ C2l, float scale2)
{
    extern __shared__ bf16 gsm[];

    const int tid  = threadIdx.x;
    const int lane = tid & 31;
    const int l16  = lane & 15;
    const int hi8  = (lane >> 4) * 8;
    const int w    = tid >> 5;
    const int wm   = w >> 1;
    const int wn   = w & 1;
    const int rowBlk = blockIdx.y * 128;
    const int colBlk = blockIdx.x * 64;

    const bool isB2 = (colBlk >= N1);
    const bf16* Bh = isB2 ? B2h : B1h;
    const bf16* Bl = isB2 ? B2l : B1l;
    const int   NB = isB2 ? N2 : N1;
    const int   cB = colBlk - (isB2 ? N1 : 0);

    const int aRow = tid >> 2;
    const int aCol = (tid & 3) * 8;
    const int bRow = tid >> 3;
    const int bCol = (tid & 7) * 8;
    // B x4T: lanes 16-31 read the lo region
    const int bLoOff = (lane >> 4) * (G_SBL - G_SBH);

    auto issue = [&](int kt, bf16* st) {
        const int k0 = kt * 32;
        #pragma unroll
        for (int i = 0; i < 2; ++i) {
            const int ar = aRow + i * 64;
            cp16(st + ar * ASTR + aCol,         Ah + (size_t)(rowBlk + ar) * K + k0 + aCol);
            cp16(st + G_SAL + ar * ASTR + aCol, Al + (size_t)(rowBlk + ar) * K + k0 + aCol);
        }
        cp16(st + G_SBH + bRow * BSTR + bCol, Bh + (size_t)(k0 + bRow) * NB + cB + bCol);
        cp16(st + G_SBL + bRow * BSTR + bCol, Bl + (size_t)(k0 + bRow) * NB + cB + bCol);
    };

    const int nk = K / 32;
    issue(0, gsm);
    CP_COMMIT();
    if (nk > 1) {
        issue(1, gsm + G_STG);
        CP_COMMIT();
    }

    float acc[2][4][4] = {};

    for (int kt = 0; kt < nk; ++kt) {
        if (kt + 1 < nk) { CP_WAIT(1); } else { CP_WAIT(0); }
        __syncthreads();

        bf16* st  = gsm + (kt & 1) * G_STG;
        bf16* sAh = st;
        bf16* sAl = st + G_SAL;
        bf16* sBh = st + G_SBH;

        #pragma unroll
        for (int s = 0; s < 2; ++s) {
            uint32_t bb[4][4];
            #pragma unroll
            for (int nt = 0; nt < 4; ++nt) {
                const int boff = (s * 16 + l16) * BSTR + wn * 32 + nt * 8 + bLoOff;
                LDSM_X4T(bb[nt], smem_addr(sBh + boff));
            }
            #pragma unroll
            for (int mt = 0; mt < 2; ++mt) {
                uint32_t ah[4], al[4];
                const int aoff = (wm * 32 + mt * 16 + l16) * ASTR + s * 16 + hi8;
                LDSM_X4(ah, smem_addr(sAh + aoff));
                LDSM_X4(al, smem_addr(sAl + aoff));
                #pragma unroll
                for (int nt = 0; nt < 4; ++nt) {
                    MMA_BF16(acc[mt][nt], ah, bb[nt][0], bb[nt][1]);
                    MMA_BF16(acc[mt][nt], ah, bb[nt][2], bb[nt][3]);
                    MMA_BF16(acc[mt][nt], al, bb[nt][0], bb[nt][1]);
                }
            }
        }
        __syncthreads();

        if (kt + 2 < nk) {
            issue(kt + 2, st);
            CP_COMMIT();
        }
    }

    bf16* Ch = isB2 ? C2h : C1h;
    bf16* Cl = isB2 ? C2l : C1l;
    const float scale = isB2 ? scale2 : scale1;

    const int rBase = rowBlk + wm * 32 + (lane >> 2);
    const int cLoc  = cB + wn * 32 + (lane & 3) * 2;
    #pragma unroll
    for (int mt = 0; mt < 2; ++mt) {
        const int r0 = rBase + mt * 16;
        const int r1 = r0 + 8;
        #pragma unroll
        for (int nt = 0; nt < 4; ++nt) {
            const int c = cLoc + nt * 8;
            float v00 = acc[mt][nt][0], v01 = acc[mt][nt][1];
            float v10 = acc[mt][nt][2], v11 = acc[mt][nt][3];
            if (Cf) {
                const float b0 = bias ? bias[c] : 0.f;
                const float b1 = bias ? bias[c + 1] : 0.f;
                *(float2*)(Cf + (size_t)r0 * N1 + c) = make_float2(v00 + b0, v01 + b1);
                *(float2*)(Cf + (size_t)r1 * N1 + c) = make_float2(v10 + b0, v11 + b1);
            } else {
                v00 *= scale; v01 *= scale; v10 *= scale; v11 *= scale;
                uint32_t h0 = pack2(v00, v01);
                float2 f0 = unpack2(h0);
                uint32_t l0 = pack2(v00 - f0.x, v01 - f0.y);
                uint32_t h1 = pack2(v10, v11);
                float2 f1 = unpack2(h1);
                uint32_t l1 = pack2(v10 - f1.x, v11 - f1.y);
                *(uint32_t*)(Ch + (size_t)r0 * NB + c) = h0;
                *(uint32_t*)(Cl + (size_t)r0 * NB + c) = l0;
                *(uint32_t*)(Ch + (size_t)r1 * NB + c) = h1;
                *(uint32_t*)(Cl + (size_t)r1 * NB + c) = l1;
            }
        }
    }
}

// ---------------------------------------------------------------------------
// Flash attention: 128q x 32k tiles, 8 warps, cp.async double buffer,
// 3 CTAs/SM (smem 73,728 B). Base-2 softmax with ex2.approx.
// smem (bf16 elems): Qh@0 (9216), Ql@9216; stages @18432 + s*9216:
//   {Kh@0 (2304), Kl@2304, Vh@4608, Vl@6912}
// ---------------------------------------------------------------------------
#define LSTR 72
#define SQH  0
#define SQL  9216
#define STG0 18432
#define STG_SZ 9216
#define ATTN_SMEM_BYTES (36864 * 2)

__global__ __launch_bounds__(256, 3)
void attn_mma_kernel(const bf16* __restrict__ Qh, const bf16* __restrict__ Ql,
                     const bf16* __restrict__ KVh, const bf16* __restrict__ KVl,
                     bf16* __restrict__ Oh, bf16* __restrict__ Ol)
{
    extern __shared__ bf16 sm[];

    const int tid  = threadIdx.x;
    const int lane = tid & 31;
    const int w    = tid >> 5;
    const int qBase = blockIdx.x * 128;
    const int h     = blockIdx.y;
    const int b     = blockIdx.z;

    const bf16* gkvh = KVh + (size_t)b * SEQ * KVW;
    const bf16* gkvl = KVl + (size_t)b * SEQ * KVW;

    const int kvRow = tid >> 3;          // 0..31
    const int kvC   = (tid & 7) * 8;
    auto issue_kv = [&](int kt, bf16* base) {
        const size_t g = (size_t)(kt * 32 + kvRow) * KVW + kvC;
        bf16* d = base + kvRow * LSTR + kvC;
        cp16(d,        gkvh + g);
        cp16(d + 2304, gkvl + g);
        cp16(d + 4608, gkvh + g + HDIM);
        cp16(d + 6912, gkvl + g + HDIM);
    };

    issue_kv(0, sm + STG0);
    CP_COMMIT();
    issue_kv(1, sm + STG0 + STG_SZ);
    CP_COMMIT();

    {
        const bf16* gqh = Qh + (size_t)(b * SEQ + qBase) * DIM + h * HDIM;
        const bf16* gql = Ql + (size_t)(b * SEQ + qBase) * DIM + h * HDIM;
        #pragma unroll
        for (int j = 0; j < 4; ++j) {
            const int idx = tid + j * 256;
            const int row = idx >> 3;
            const int c   = (idx & 7) * 8;
            *(uint4*)(sm + SQH + row * LSTR + c) = *(const uint4*)(gqh + (size_t)row * DIM + c);
            *(uint4*)(sm + SQL + row * LSTR + c) = *(const uint4*)(gql + (size_t)row * DIM + c);
        }
    }

    float oc[8][4] = {};
    float m0 = -1e30f, m1 = -1e30f, l0 = 0.f, l1 = 0.f;

    const int l16 = lane & 15;
    const int aRow = w * 16 + l16;
    const int aColBase = (lane >> 4) * 8;
    const int kRowOff = (l16 & 7) + ((lane >> 4) << 3);
    const int kColOff = ((l16 >> 3) & 1) * 8;
    const int vRow = l16;
    const int vColOff = (lane >> 4) * 8;

    const int NK = SEQ / 32;   // 64
    for (int kt = 0; kt < NK; ++kt) {
        bf16* cur = sm + STG0 + (kt & 1) * STG_SZ;
        if (kt + 1 < NK) { CP_WAIT(1); } else { CP_WAIT(0); }
        __syncthreads();

        bf16* sKh = cur;
        bf16* sKl = cur + 2304;
        bf16* sVh = cur + 4608;
        bf16* sVl = cur + 6912;

        // ---- S = Q K^T (32 keys) ----
        float sc[4][4] = {};
        #pragma unroll
        for (int ks = 0; ks < 4; ++ks) {
            uint32_t aqh[4], aql[4];
            LDSM_X4(aqh, smem_addr(sm + SQH + aRow * LSTR + ks * 16 + aColBase));
            LDSM_X4(aql, smem_addr(sm + SQL + aRow * LSTR + ks * 16 + aColBase));
            #pragma unroll
            for (int ntp = 0; ntp < 2; ++ntp) {
                uint32_t bkh[4], bkl[4];
                const int boff = (ntp * 16 + kRowOff) * LSTR + ks * 16 + kColOff;
                LDSM_X4(bkh, smem_addr(sKh + boff));
                LDSM_X4(bkl, smem_addr(sKl + boff));
                MMA_BF16(sc[2*ntp],   aqh, bkh[0], bkh[1]);
                MMA_BF16(sc[2*ntp],   aqh, bkl[0], bkl[1]);
                MMA_BF16(sc[2*ntp],   aql, bkh[0], bkh[1]);
                MMA_BF16(sc[2*ntp+1], aqh, bkh[2], bkh[3]);
                MMA_BF16(sc[2*ntp+1], aqh, bkl[2], bkl[3]);
                MMA_BF16(sc[2*ntp+1], aql, bkh[2], bkh[3]);
            }
        }

        // ---- online softmax (base 2, ex2.approx) ----
        float mx0 = -1e30f, mx1 = -1e30f;
        #pragma unroll
        for (int nt = 0; nt < 4; ++nt) {
            mx0 = fmaxf(mx0, fmaxf(sc[nt][0], sc[nt][1]));
            mx1 = fmaxf(mx1, fmaxf(sc[nt][2], sc[nt][3]));
        }
        mx0 = fmaxf(mx0, __shfl_xor_sync(0xffffffffu, mx0, 1));
        mx0 = fmaxf(mx0, __shfl_xor_sync(0xffffffffu, mx0, 2));
        mx1 = fmaxf(mx1, __shfl_xor_sync(0xffffffffu, mx1, 1));
        mx1 = fmaxf(mx1, __shfl_xor_sync(0xffffffffu, mx1, 2));
        const float mn0 = fmaxf(m0, mx0);
        const float mn1 = fmaxf(m1, mx1);
        float cr0, cr1;
        EX2F(cr0, m0 - mn0);
        EX2F(cr1, m1 - mn1);
        m0 = mn0; m1 = mn1;

        float s0 = 0.f, s1 = 0.f;
        #pragma unroll
        for (int nt = 0; nt < 4; ++nt) {
            EX2F(sc[nt][0], sc[nt][0] - mn0);
            EX2F(sc[nt][1], sc[nt][1] - mn0);
            EX2F(sc[nt][2], sc[nt][2] - mn1);
            EX2F(sc[nt][3], sc[nt][3] - mn1);
            s0 += sc[nt][0] + sc[nt][1];
            s1 += sc[nt][2] + sc[nt][3];
        }
        s0 += __shfl_xor_sync(0xffffffffu, s0, 1);
        s0 += __shfl_xor_sync(0xffffffffu, s0, 2);
        s1 += __shfl_xor_sync(0xffffffffu, s1, 1);
        s1 += __shfl_xor_sync(0xffffffffu, s1, 2);
        l0 = l0 * cr0 + s0;
        l1 = l1 * cr1 + s1;
        #pragma unroll
        for (int dt = 0; dt < 8; ++dt) {
            oc[dt][0] *= cr0; oc[dt][1] *= cr0;
            oc[dt][2] *= cr1; oc[dt][3] *= cr1;
        }

        // ---- O += P V (32 keys = 2 k16 groups) ----
        #pragma unroll
        for (int g = 0; g < 2; ++g) {
            const int t0 = 2 * g, t1 = 2 * g + 1;
            uint32_t ah[4], al[4];
            ah[0] = pack2(sc[t0][0], sc[t0][1]);
            ah[1] = pack2(sc[t0][2], sc[t0][3]);
            ah[2] = pack2(sc[t1][0], sc[t1][1]);
            ah[3] = pack2(sc[t1][2], sc[t1][3]);
            {
                float2 f;
                f = unpack2(ah[0]); al[0] = pack2(sc[t0][0] - f.x, sc[t0][1] - f.y);
                f = unpack2(ah[1]); al[1] = pack2(sc[t0][2] - f.x, sc[t0][3] - f.y);
                f = unpack2(ah[2]); al[2] = pack2(sc[t1][0] - f.x, sc[t1][1] - f.y);
                f = unpack2(ah[3]); al[3] = pack2(sc[t1][2] - f.x, sc[t1][3] - f.y);
            }
            #pragma unroll
            for (int dtp = 0; dtp < 4; ++dtp) {
                uint32_t vh4[4], vl4[4];
                const int voff = (g * 16 + vRow) * LSTR + dtp * 16 + vColOff;
                LDSM_X4T(vh4, smem_addr(sVh + voff));
                LDSM_X4T(vl4, smem_addr(sVl + voff));
                MMA_BF16(oc[2*dtp],   ah, vh4[0], vh4[1]);
                MMA_BF16(oc[2*dtp],   ah, vl4[0], vl4[1]);
                MMA_BF16(oc[2*dtp],   al, vh4[0], vh4[1]);
                MMA_BF16(oc[2*dtp+1], ah, vh4[2], vh4[3]);
                MMA_BF16(oc[2*dtp+1], ah, vl4[2], vl4[3]);
                MMA_BF16(oc[2*dtp+1], al, vh4[2], vh4[3]);
            }
        }
        __syncthreads();

        if (kt + 2 < NK) {
            issue_kv(kt + 2, cur);
            CP_COMMIT();
        }
    }

    // ---- normalize + split-bf16 store ----
    const float inv0 = 1.f / l0;
    const float inv1 = 1.f / l1;
    const int r0 = w * 16 + (lane >> 2);
    const int r1 = r0 + 8;
    const size_t base0 = (size_t)(b * SEQ + qBase + r0) * DIM + h * HDIM;
    const size_t base1 = (size_t)(b * SEQ + qBase + r1) * DIM + h * HDIM;
    #pragma unroll
    for (int dt = 0; dt < 8; ++dt) {
        const int col = dt * 8 + (lane & 3) * 2;
        const float v00 = oc[dt][0] * inv0, v01 = oc[dt][1] * inv0;
        const float v10 = oc[dt][2] * inv1, v11 = oc[dt][3] * inv1;
        uint32_t h0 = pack2(v00, v01);
        float2 f0 = unpack2(h0);
        uint32_t l0w = pack2(v00 - f0.x, v01 - f0.y);
        uint32_t h1 = pack2(v10, v11);
        float2 f1 = unpack2(h1);
        uint32_t l1w = pack2(v10 - f1.x, v11 - f1.y);
        *(uint32_t*)(Oh + base0 + col) = h0;
        *(uint32_t*)(Ol + base0 + col) = l0w;
        *(uint32_t*)(Oh + base1 + col) = h1;
        *(uint32_t*)(Ol + base1 + col) = l1w;
    }
}

// ---------------------------------------------------------------------------
extern "C" void kernel_launch(void* const* d_in, const int* in_sizes, int n_in,
                              void* d_out, int out_size)
{
    const float* x     = (const float*)d_in[0];
    const float* Wq    = (const float*)d_in[1];
    const float* Wkv   = (const float*)d_in[2];
    const float* Wproj = (const float*)d_in[3];
    const float* bproj = (const float*)d_in[4];
    float* out = (float*)d_out;

    bf16 *xh, *xl, *Wqh, *Wql, *Wkh, *Wkl, *Wph, *Wpl;
    bf16 *Qh, *Ql, *KVh, *KVl, *Oh, *Ol;
    cudaGetSymbolAddress((void**)&xh,  g_xh);  cudaGetSymbolAddress((void**)&xl,  g_xl);
    cudaGetSymbolAddress((void**)&Wqh, g_Wqh); cudaGetSymbolAddress((void**)&Wql, g_Wql);
    cudaGetSymbolAddress((void**)&Wkh, g_Wkh); cudaGetSymbolAddress((void**)&Wkl, g_Wkl);
    cudaGetSymbolAddress((void**)&Wph, g_Wph); cudaGetSymbolAddress((void**)&Wpl, g_Wpl);
    cudaGetSymbolAddress((void**)&Qh,  g_Qh);  cudaGetSymbolAddress((void**)&Ql,  g_Ql);
    cudaGetSymbolAddress((void**)&KVh, g_KVh); cudaGetSymbolAddress((void**)&KVl, g_KVl);
    cudaGetSymbolAddress((void**)&Oh,  g_Oh);  cudaGetSymbolAddress((void**)&Ol,  g_Ol);

    static bool attr_set = false;
    if (!attr_set) {
        cudaFuncSetAttribute(attn_mma_kernel,
                             cudaFuncAttributeMaxDynamicSharedMemorySize,
                             ATTN_SMEM_BYTES);
        cudaFuncSetAttribute(gemm_bf16,
                             cudaFuncAttributeMaxDynamicSharedMemorySize,
                             GEMM_SMEM_BYTES);
        attr_set = true;
    }

    // 0) fused split conversion
    cvt_all<<<CVT_TOTAL / 256, 256>>>(x, Wq, Wkv, Wproj,
                                      xh, xl, Wqh, Wql, Wkh, Wkl, Wph, Wpl);

    // 1) fused Q|KV projection (Q scaled by 0.125*log2(e))
    {
        dim3 grid((DIM + KVW) / 64, MROWS / 128);
        gemm_bf16<<<grid, 256, GEMM_SMEM_BYTES>>>(xh, xl,
                                 Wqh, Wql, DIM, Wkh, Wkl, KVW,
                                 MROWS, DIM,
                                 nullptr, nullptr,
                                 Qh, Ql, ATT_SCALE_LOG2E,
                                 KVh, KVl, 1.0f);
    }
    // 2) flash attention (base-2 softmax)
    {
        dim3 grid(SEQ / 128, NHEAD, BATCH);
        attn_mma_kernel<<<grid, 256, ATTN_SMEM_BYTES>>>(Qh, Ql, KVh, KVl, Oh, Ol);
    }
    // 3) out = O @ Wproj + bproj
    {
        dim3 grid(DIM / 64, MROWS / 128);
        gemm_bf16<<<grid, 256, GEMM_SMEM_BYTES>>>(Oh, Ol,
                                 Wph, Wpl, DIM, nullptr, nullptr, 0,
                                 MROWS, DIM,
                                 out, bproj,
                                 nullptr, nullptr, 1.0f,
                                 nullptr, nullptr, 1.0f);
    }
}